// round 2
// baseline (speedup 1.0000x reference)
#include <cuda_runtime.h>

#define Z 64      // z_dim
#define H 256     // hidden
#define C 5       // num classes
#define GMAX 16
#define MAXBLK 96

// partial class sums: layout [g][c][blk][d]
__device__ __align__(16) float g_part[GMAX * C * MAXBLK * Z];
__device__ int   g_cntp[MAXBLK * C];
__device__ __align__(16) float g_D[GMAX * C * Z];

// ------------------------------------------------------- per-class sum of x
// grid: (nblk, G+1). blockIdx.y == G -> label counting blocks.
// 256 threads = 16 groups of 16 lanes; lane = float4 chunk of dim, group strides nodes.
__global__ void reduce_kernel(const float* __restrict__ x,
                              const int*   __restrict__ label,
                              int N, int chunk, int nblk) {
    int g  = blockIdx.y;
    int bx = blockIdx.x;
    int n0 = bx * chunk;
    int n1 = min(n0 + chunk, N);
    int tid = threadIdx.x;

    if (g == (int)gridDim.y - 1) {
        // counting block: partial counts for this chunk
        int cnt[C];
#pragma unroll
        for (int c = 0; c < C; c++) cnt[c] = 0;
        for (int n = n0 + tid; n < n1; n += blockDim.x) {
            int c = __ldg(label + n);
#pragma unroll
            for (int cc = 0; cc < C; cc++) cnt[cc] += (cc == c);
        }
        __shared__ int scnt[C];
        if (tid < C) scnt[tid] = 0;
        __syncthreads();
#pragma unroll
        for (int cc = 0; cc < C; cc++)
            if (cnt[cc]) atomicAdd(&scnt[cc], cnt[cc]);
        __syncthreads();
        if (tid < C) g_cntp[bx * C + tid] = scnt[tid];
        return;
    }

    int lane = tid & 15;   // float4 index within 64-dim row
    int grp  = tid >> 4;   // 16 node-groups

    float4 acc[C];
#pragma unroll
    for (int c = 0; c < C; c++) acc[c] = make_float4(0.f, 0.f, 0.f, 0.f);

    const float4* x4 = reinterpret_cast<const float4*>(x) + (size_t)g * N * 16;

#pragma unroll 2
    for (int n = n0 + grp; n < n1; n += 16) {
        int    c = __ldg(label + n);
        float4 v = __ldg(x4 + (size_t)n * 16 + lane);
#pragma unroll
        for (int cc = 0; cc < C; cc++) {
            if (c == cc) {
                acc[cc].x += v.x;
                acc[cc].y += v.y;
                acc[cc].z += v.z;
                acc[cc].w += v.w;
            }
        }
    }

    __shared__ float4 sacc[16][C][16];
#pragma unroll
    for (int c = 0; c < C; c++) sacc[grp][c][lane] = acc[c];
    __syncthreads();

    if (tid < C * 16) {
        int c = tid >> 4, d4 = tid & 15;
        float4 s = sacc[0][c][d4];
#pragma unroll
        for (int g2 = 1; g2 < 16; g2++) {
            float4 t = sacc[g2][c][d4];
            s.x += t.x; s.y += t.y; s.z += t.z; s.w += t.w;
        }
        float4* P4 = reinterpret_cast<float4*>(g_part);
        P4[((size_t)(g * C + c) * nblk + bx) * 16 + d4] = s;
    }
}

// ----------------------------------------- sum partials + tiny 2-layer GEMM
// block r = g*C + c computes D[r,:] = relu((S[r]/cnt) @ W1 + b1) @ W2 + b2
__global__ void mid_kernel(const float* __restrict__ W1,
                           const float* __restrict__ b1,
                           const float* __restrict__ W2,
                           const float* __restrict__ b2,
                           int nblk) {
    int r   = blockIdx.x;
    int g   = r / C;
    int c   = r % C;
    int tid = threadIdx.x;

    __shared__ int   scnt;
    __shared__ float s[Z];
    __shared__ float h[H];
    __shared__ float part[4][Z];

    if (tid == 0) scnt = 0;
    __syncthreads();
    if (tid < nblk) atomicAdd(&scnt, g_cntp[tid * C + c]);

    // sum partial class sums
    const float* P = g_part + (size_t)(g * C + c) * nblk * Z;
    int d = tid & 63, j = tid >> 6;
    float p = 0.f;
    for (int b = j; b < nblk; b += 4) p += P[b * Z + d];
    part[j][d] = p;
    __syncthreads();

    float inv = 1.f / (float)max(scnt, 1);
    if (tid < Z)
        s[tid] = (part[0][tid] + part[1][tid] + part[2][tid] + part[3][tid]) * inv;
    __syncthreads();

    // layer 1: h[j] = relu(sum_d s[d] * W1[d,j] + b1[j]), tid = j
    float acc = __ldg(b1 + tid);
#pragma unroll
    for (int dd = 0; dd < Z; dd++)
        acc = fmaf(s[dd], __ldg(W1 + dd * H + tid), acc);
    h[tid] = fmaxf(acc, 0.f);
    __syncthreads();

    // layer 2: D[k] = sum_j h[j] * W2[j,k] + b2[k]
    int lane = tid & 63, grp = tid >> 6;
    float p2 = 0.f;
#pragma unroll
    for (int jj = 0; jj < 64; jj++) {
        int jidx = grp * 64 + jj;
        p2 = fmaf(h[jidx], __ldg(W2 + jidx * Z + lane), p2);
    }
    __syncthreads();
    part[grp][lane] = p2;
    __syncthreads();
    if (tid < Z) {
        float dv = __ldg(b2 + tid) + part[0][tid] + part[1][tid]
                 + part[2][tid] + part[3][tid];
        g_D[r * Z + tid] = dv;
    }
}

// ------------------------------------ out[g,n,:] = x[g,n,:] + D[g,label[n],:]
// float4 path: 16 lanes cover one 64-float row, 16 groups stride rows.
__global__ void out_kernel(const float* __restrict__ x,
                           const int*   __restrict__ label,
                           float*       __restrict__ out,
                           int N, int chunk) {
    int g = blockIdx.y;
    __shared__ float4 sD[C * 16];
    if (threadIdx.x < C * 16)
        sD[threadIdx.x] =
            reinterpret_cast<const float4*>(g_D)[g * C * 16 + threadIdx.x];
    __syncthreads();

    int lane = threadIdx.x & 15;
    int grp  = threadIdx.x >> 4;
    int n0 = blockIdx.x * chunk;
    int n1 = min(n0 + chunk, N);

    const float4* x4 = reinterpret_cast<const float4*>(x);
    float4*       o4 = reinterpret_cast<float4*>(out);

#pragma unroll 4
    for (int n = n0 + grp; n < n1; n += 16) {
        int    c   = __ldg(label + n);
        size_t idx = ((size_t)g * N + n) * 16 + lane;
        float4 xv  = __ldg(x4 + idx);
        float4 dv  = sD[c * 16 + lane];
        float4 rv;
        rv.x = xv.x + dv.x;
        rv.y = xv.y + dv.y;
        rv.z = xv.z + dv.z;
        rv.w = xv.w + dv.w;
        o4[idx] = rv;
    }
}

// ---------------------------------------------------------------- launcher
extern "C" void kernel_launch(void* const* d_in, const int* in_sizes, int n_in,
                              void* d_out, int out_size) {
    const float* x     = (const float*)d_in[0];
    const int*   label = (const int*)  d_in[1];
    const float* W1    = (const float*)d_in[2];
    const float* b1    = (const float*)d_in[3];
    const float* W2    = (const float*)d_in[4];
    const float* b2    = (const float*)d_in[5];
    float*       out   = (float*)d_out;

    int N = in_sizes[1];                 // 40000
    int G = in_sizes[0] / (N * Z);       // 16

    // chunk multiple of 16; cap nblk at MAXBLK
    int chunk1 = 512;
    int nblk = (N + chunk1 - 1) / chunk1;
    if (nblk > MAXBLK) {
        chunk1 = (((N + MAXBLK - 1) / MAXBLK) + 15) & ~15;
        nblk = (N + chunk1 - 1) / chunk1;
    }

    dim3 grid1(nblk, G + 1);
    reduce_kernel<<<grid1, 256>>>(x, label, N, chunk1, nblk);

    mid_kernel<<<G * C, 256>>>(W1, b1, W2, b2, nblk);

    int chunk3 = 320;                    // multiple of 16
    dim3 grid3((N + chunk3 - 1) / chunk3, G);
    out_kernel<<<grid3, 256>>>(x, label, out, N, chunk3);
}

// round 3
// speedup vs baseline: 1.1389x; 1.1389x over previous
#include <cuda_runtime.h>

#define Z 64      // z_dim
#define H 256     // hidden
#define C 5       // num classes
#define GMAX 16
#define MAXBLK 96

// partial class sums: layout [g][c][blk][d]
__device__ __align__(16) float g_part[GMAX * C * MAXBLK * Z];
__device__ int   g_cntp[MAXBLK * C];
__device__ __align__(16) float g_D[GMAX * C * Z];

// ------------------------------------------------------- per-class sum of x
// grid: (nblk, G+1). blockIdx.y == G -> label counting blocks.
// 256 threads = 16 groups of 16 lanes; lane = float4 chunk of dim, group strides nodes.
__global__ void __launch_bounds__(256, 6)
reduce_kernel(const float* __restrict__ x,
              const int*   __restrict__ label,
              int N, int chunk, int nblk) {
    int g  = blockIdx.y;
    int bx = blockIdx.x;
    int n0 = bx * chunk;
    int n1 = min(n0 + chunk, N);
    int tid = threadIdx.x;

    if (g == (int)gridDim.y - 1) {
        // counting block: partial counts for this chunk
        int cnt[C];
#pragma unroll
        for (int c = 0; c < C; c++) cnt[c] = 0;
        for (int n = n0 + tid; n < n1; n += blockDim.x) {
            int c = __ldg(label + n);
#pragma unroll
            for (int cc = 0; cc < C; cc++) cnt[cc] += (cc == c);
        }
        __shared__ int scnt[C];
        if (tid < C) scnt[tid] = 0;
        __syncthreads();
#pragma unroll
        for (int cc = 0; cc < C; cc++)
            if (cnt[cc]) atomicAdd(&scnt[cc], cnt[cc]);
        __syncthreads();
        if (tid < C) g_cntp[bx * C + tid] = scnt[tid];
        return;
    }

    int lane = tid & 15;   // float4 index within 64-dim row
    int grp  = tid >> 4;   // 16 node-groups

    float4 acc[C];
#pragma unroll
    for (int c = 0; c < C; c++) acc[c] = make_float4(0.f, 0.f, 0.f, 0.f);

    const float4* x4 = reinterpret_cast<const float4*>(x) + (size_t)g * N * 16;

    // chunk is a multiple of 32 -> (n1-n0) iterations per group come in pairs,
    // except possibly in the final block; handle pair + scalar tail.
    int n = n0 + grp;
    for (; n + 16 < n1; n += 32) {
        int    c0 = __ldg(label + n);
        int    c1 = __ldg(label + n + 16);
        float4 v0 = __ldg(x4 + (size_t)n * 16 + lane);
        float4 v1 = __ldg(x4 + (size_t)(n + 16) * 16 + lane);
#pragma unroll
        for (int cc = 0; cc < C; cc++) {
            if (c0 == cc) {
                acc[cc].x += v0.x; acc[cc].y += v0.y;
                acc[cc].z += v0.z; acc[cc].w += v0.w;
            }
            if (c1 == cc) {
                acc[cc].x += v1.x; acc[cc].y += v1.y;
                acc[cc].z += v1.z; acc[cc].w += v1.w;
            }
        }
    }
    if (n < n1) {
        int    c0 = __ldg(label + n);
        float4 v0 = __ldg(x4 + (size_t)n * 16 + lane);
#pragma unroll
        for (int cc = 0; cc < C; cc++) {
            if (c0 == cc) {
                acc[cc].x += v0.x; acc[cc].y += v0.y;
                acc[cc].z += v0.z; acc[cc].w += v0.w;
            }
        }
    }

    __shared__ float4 sacc[16][C][16];
#pragma unroll
    for (int c = 0; c < C; c++) sacc[grp][c][lane] = acc[c];
    __syncthreads();

    if (tid < C * 16) {
        int c = tid >> 4, d4 = tid & 15;
        float4 s = sacc[0][c][d4];
#pragma unroll
        for (int g2 = 1; g2 < 16; g2++) {
            float4 t = sacc[g2][c][d4];
            s.x += t.x; s.y += t.y; s.z += t.z; s.w += t.w;
        }
        float4* P4 = reinterpret_cast<float4*>(g_part);
        P4[((size_t)(g * C + c) * nblk + bx) * 16 + d4] = s;
    }
}

// ----------------------------------------- sum partials + tiny 2-layer GEMM
// block r = g*C + c computes D[r,:] = relu((S[r]/cnt) @ W1 + b1) @ W2 + b2
__global__ void mid_kernel(const float* __restrict__ W1,
                           const float* __restrict__ b1,
                           const float* __restrict__ W2,
                           const float* __restrict__ b2,
                           int nblk) {
    int r   = blockIdx.x;
    int g   = r / C;
    int c   = r % C;
    int tid = threadIdx.x;

    __shared__ int   scnt;
    __shared__ float s[Z];
    __shared__ float h[H];
    __shared__ float part[4][Z];

    if (tid == 0) scnt = 0;
    __syncthreads();
    if (tid < nblk) atomicAdd(&scnt, g_cntp[tid * C + c]);

    // sum partial class sums
    const float* P = g_part + (size_t)(g * C + c) * nblk * Z;
    int d = tid & 63, j = tid >> 6;
    float p = 0.f;
    for (int b = j; b < nblk; b += 4) p += P[b * Z + d];
    part[j][d] = p;
    __syncthreads();

    float inv = 1.f / (float)max(scnt, 1);
    if (tid < Z)
        s[tid] = (part[0][tid] + part[1][tid] + part[2][tid] + part[3][tid]) * inv;
    __syncthreads();

    // layer 1: h[j] = relu(sum_d s[d] * W1[d,j] + b1[j]), tid = j
    float acc = __ldg(b1 + tid);
#pragma unroll
    for (int dd = 0; dd < Z; dd++)
        acc = fmaf(s[dd], __ldg(W1 + dd * H + tid), acc);
    h[tid] = fmaxf(acc, 0.f);
    __syncthreads();

    // layer 2: D[k] = sum_j h[j] * W2[j,k] + b2[k]
    int lane = tid & 63, grp = tid >> 6;
    float p2 = 0.f;
#pragma unroll
    for (int jj = 0; jj < 64; jj++) {
        int jidx = grp * 64 + jj;
        p2 = fmaf(h[jidx], __ldg(W2 + jidx * Z + lane), p2);
    }
    __syncthreads();
    part[grp][lane] = p2;
    __syncthreads();
    if (tid < Z) {
        float dv = __ldg(b2 + tid) + part[0][tid] + part[1][tid]
                 + part[2][tid] + part[3][tid];
        g_D[r * Z + tid] = dv;
    }
}

// ------------------------------------ out[g,n,:] = x[g,n,:] + D[g,label[n],:]
// float4 path: 16 lanes cover one 64-float row, 16 groups stride rows.
// Traversal is REVERSED (high g / high n first) so the second read of x hits
// the L2 residue left by reduce_kernel's forward scan.
__global__ void out_kernel(const float* __restrict__ x,
                           const int*   __restrict__ label,
                           float*       __restrict__ out,
                           int N, int chunk) {
    int g  = (int)gridDim.y - 1 - blockIdx.y;            // reversed graph order
    int bx = (int)gridDim.x - 1 - blockIdx.x;            // reversed chunk order

    __shared__ float4 sD[C * 16];
    if (threadIdx.x < C * 16)
        sD[threadIdx.x] =
            reinterpret_cast<const float4*>(g_D)[g * C * 16 + threadIdx.x];
    __syncthreads();

    int lane = threadIdx.x & 15;
    int grp  = threadIdx.x >> 4;
    int n0 = bx * chunk;
    int n1 = min(n0 + chunk, N);

    const float4* x4 = reinterpret_cast<const float4*>(x);
    float4*       o4 = reinterpret_cast<float4*>(out);

#pragma unroll 4
    for (int n = n0 + grp; n < n1; n += 16) {
        int    c   = __ldg(label + n);
        size_t idx = ((size_t)g * N + n) * 16 + lane;
        float4 xv  = __ldg(x4 + idx);
        float4 dv  = sD[c * 16 + lane];
        float4 rv;
        rv.x = xv.x + dv.x;
        rv.y = xv.y + dv.y;
        rv.z = xv.z + dv.z;
        rv.w = xv.w + dv.w;
        o4[idx] = rv;
    }
}

// ---------------------------------------------------------------- launcher
extern "C" void kernel_launch(void* const* d_in, const int* in_sizes, int n_in,
                              void* d_out, int out_size) {
    const float* x     = (const float*)d_in[0];
    const int*   label = (const int*)  d_in[1];
    const float* W1    = (const float*)d_in[2];
    const float* b1    = (const float*)d_in[3];
    const float* W2    = (const float*)d_in[4];
    const float* b2    = (const float*)d_in[5];
    float*       out   = (float*)d_out;

    int N = in_sizes[1];                 // 40000
    int G = in_sizes[0] / (N * Z);       // 16

    // Single balanced wave: 6 blocks/SM * 148 SMs = 888 slots.
    // chunk multiple of 32; pick nblk so (G+1)*nblk <= 888.
    int chunk1 = 864;
    int nblk = (N + chunk1 - 1) / chunk1;          // 47 for N=40000
    while ((G + 1) * nblk > 888 || nblk > MAXBLK) {
        chunk1 += 32;
        nblk = (N + chunk1 - 1) / chunk1;
    }

    dim3 grid1(nblk, G + 1);
    reduce_kernel<<<grid1, 256>>>(x, label, N, chunk1, nblk);

    mid_kernel<<<G * C, 256>>>(W1, b1, W2, b2, nblk);

    int chunk3 = 320;                    // multiple of 16
    dim3 grid3((N + chunk3 - 1) / chunk3, G);
    out_kernel<<<grid3, 256>>>(x, label, out, N, chunk3);
}